// round 9
// baseline (speedup 1.0000x reference)
#include <cuda_runtime.h>
#include <math.h>
#include <stdint.h>

#define T_TOK 4096
#define H     2048
#define IDIM  1024
#define NE    8
#define NTOT  12
#define CAP   4096
#define SCALE 1.5f

// ---------------- scratch (static device globals; no runtime allocation) ----------------
__device__ int   g_cnt[NE];
__device__ int   g_tok[NE * CAP];
__device__ float g_wt [NE * CAP];
__device__ int   g_dst[NE * CAP];
__device__ float g_zw [T_TOK];
__device__ int   g_mask[T_TOK];
__device__ float g_act [(size_t)NE * CAP * IDIM];     // expert-grouped activations
__device__ float g_pair[(size_t)T_TOK * 2 * H];       // per (token,k) down output

// ---------------- helpers ----------------
__device__ __forceinline__ void cp_async16(void* smem, const void* gmem) {
    uint32_t s = (uint32_t)__cvta_generic_to_shared(smem);
    asm volatile("cp.async.cg.shared.global [%0], [%1], 16;" :: "r"(s), "l"(gmem));
}
#define CP_COMMIT() asm volatile("cp.async.commit_group;")
#define CP_WAIT2()  asm volatile("cp.async.wait_group 2;")

__device__ __forceinline__ uint32_t f2tf32(float f) {
    uint32_t r;
    asm("cvt.rna.tf32.f32 %0, %1;" : "=r"(r) : "f"(f));
    return r;
}

__device__ __forceinline__ void mma_tf32(float c[4],
                                         uint32_t a0, uint32_t a1, uint32_t a2, uint32_t a3,
                                         uint32_t b0, uint32_t b1) {
    asm volatile(
        "mma.sync.aligned.m16n8k8.row.col.f32.tf32.tf32.f32 "
        "{%0,%1,%2,%3}, {%4,%5,%6,%7}, {%8,%9}, {%0,%1,%2,%3};\n"
        : "+f"(c[0]), "+f"(c[1]), "+f"(c[2]), "+f"(c[3])
        : "r"(a0), "r"(a1), "r"(a2), "r"(a3), "r"(b0), "r"(b1));
}

// ---------------- router: one warp per token ----------------
__global__ void router_kernel(const float* __restrict__ x,
                              const float* __restrict__ cw,
                              const float* __restrict__ bias) {
    int warp = threadIdx.x >> 5;
    int lane = threadIdx.x & 31;
    int t = blockIdx.x * 4 + warp;
    if (t >= T_TOK) return;
    const float* xr = x + (size_t)t * H;

    float acc[NTOT];
#pragma unroll
    for (int e = 0; e < NTOT; e++) acc[e] = 0.f;
    for (int h = lane; h < H; h += 32) {
        float xv = xr[h];
#pragma unroll
        for (int e = 0; e < NTOT; e++) acc[e] += xv * __ldg(&cw[e * H + h]);
    }
#pragma unroll
    for (int e = 0; e < NTOT; e++) {
#pragma unroll
        for (int off = 16; off; off >>= 1)
            acc[e] += __shfl_xor_sync(0xffffffffu, acc[e], off);
    }
    if (lane == 0) {
        float m = acc[0];
#pragma unroll
        for (int e = 1; e < NTOT; e++) m = fmaxf(m, acc[e]);
        float p[NTOT];
        float s = 0.f;
#pragma unroll
        for (int e = 0; e < NTOT; e++) { p[e] = expf(acc[e] - m); s += p[e]; }
        float inv = 1.f / s;
        float biased[NTOT];
#pragma unroll
        for (int e = 0; e < NTOT; e++) { p[e] *= inv; biased[e] = p[e] + bias[e]; }

        // top-2 of biased scores (lowest index wins ties, matching jax.lax.top_k)
        int i0 = 0;
#pragma unroll
        for (int e = 1; e < NTOT; e++) if (biased[e] > biased[i0]) i0 = e;
        int i1 = (i0 == 0) ? 1 : 0;
#pragma unroll
        for (int e = 0; e < NTOT; e++)
            if (e != i0 && biased[e] > biased[i1]) i1 = e;

        int sel[2] = { i0, i1 };
        float zw = 0.f;
        int mask = 0;
#pragma unroll
        for (int k = 0; k < 2; k++) {
            int e = sel[k];
            float w = p[e] * SCALE;       // weight uses UNBIASED prob
            if (e < NE) {
                int slot = atomicAdd(&g_cnt[e], 1);
                g_tok[e * CAP + slot] = t;
                g_wt [e * CAP + slot] = w;
                g_dst[e * CAP + slot] = t * 2 + k;
                mask |= (1 << k);
            } else {
                zw += w;
            }
        }
        g_zw[t]  = zw;
        g_mask[t] = mask;
    }
}

// ---------------- grouped gate+up tf32 GEMM, big warp tiles ----------------
// Block tile: 128 slots x 128 inter, BK=16. 8 warps (2x4). Warp tile 64x32 for
// BOTH gate and up (shared A fragments). 4-stage cp.async, dynamic smem.
#define GU_BM 128
#define GU_BN 128
#define GU_BK 16
#define GU_IT (H / GU_BK)
#define SMS 20          // k-stride (16 + 4 pad) -> conflict-free fragment LDS
#define NSTG 4

#define GU_T_ST (GU_BM * SMS)                 // one tensor, one stage (floats) = 2560
#define GU_SMEM_BYTES ((NSTG * 3 * GU_T_ST) * 4 + GU_BM * 4)

__global__ __launch_bounds__(256, 1) void gateup_kernel(const float* __restrict__ x,
                                                        const float* __restrict__ gw,
                                                        const float* __restrict__ uw) {
    int e = blockIdx.z;
    int cnt = g_cnt[e];
    int t0 = blockIdx.y * GU_BM;
    if (t0 >= cnt) return;
    int i0 = blockIdx.x * GU_BN;

    extern __shared__ float dsm[];
    float* SA = dsm;                               // [NSTG][128][SMS]
    float* SG = SA + NSTG * GU_T_ST;               // [NSTG][128][SMS]
    float* SU = SG + NSTG * GU_T_ST;               // [NSTG][128][SMS]
    int*   toks = (int*)(SU + NSTG * GU_T_ST);     // [GU_BM]

    int tid  = threadIdx.x;
    int lane = tid & 31;
    int warp = tid >> 5;
    int wm = warp >> 2;       // 0..1  (64 rows each)
    int wn = warp & 3;        // 0..3  (32 cols each)
    int g = lane >> 2;        // 0..7
    int tg = lane & 3;        // 0..3

    if (tid < GU_BM) {
        int s = t0 + tid;
        toks[tid] = g_tok[e * CAP + ((s < cnt) ? s : 0)];
    }
    __syncthreads();

    // staging: 2 threads per row, each covers 8 floats (2 cp.async)
    int r0 = tid >> 1;             // 0..127
    int ch = (tid & 1) * 8;        // 0 or 8

    const float* aP = x + (size_t)toks[r0] * H + ch;
    const float* gP = gw + (size_t)e * IDIM * H + (size_t)(i0 + r0) * H + ch;
    const float* uP = uw + (size_t)e * IDIM * H + (size_t)(i0 + r0) * H + ch;

    float cg[4][4][4] = {};
    float cu[4][4][4] = {};

#pragma unroll
    for (int s = 0; s < NSTG - 1; s++) {
        int ko = s * GU_BK;
        float* sa = SA + s * GU_T_ST + r0 * SMS + ch;
        float* sg = SG + s * GU_T_ST + r0 * SMS + ch;
        float* su = SU + s * GU_T_ST + r0 * SMS + ch;
        cp_async16(sa,     aP + ko);
        cp_async16(sa + 4, aP + ko + 4);
        cp_async16(sg,     gP + ko);
        cp_async16(sg + 4, gP + ko + 4);
        cp_async16(su,     uP + ko);
        cp_async16(su + 4, uP + ko + 4);
        CP_COMMIT();
    }

    for (int k = 0; k < GU_IT; k++) {
        CP_WAIT2();
        __syncthreads();

        int kn = k + NSTG - 1;
        if (kn < GU_IT) {
            int st = kn & (NSTG - 1);
            int ko = kn * GU_BK;
            float* sa = SA + st * GU_T_ST + r0 * SMS + ch;
            float* sg = SG + st * GU_T_ST + r0 * SMS + ch;
            float* su = SU + st * GU_T_ST + r0 * SMS + ch;
            cp_async16(sa,     aP + ko);
            cp_async16(sa + 4, aP + ko + 4);
            cp_async16(sg,     gP + ko);
            cp_async16(sg + 4, gP + ko + 4);
            cp_async16(su,     uP + ko);
            cp_async16(su + 4, uP + ko + 4);
        }
        CP_COMMIT();

        int st = k & (NSTG - 1);
        const float* sa = SA + st * GU_T_ST;
        const float* sg = SG + st * GU_T_ST;
        const float* su = SU + st * GU_T_ST;
#pragma unroll
        for (int ks = 0; ks < GU_BK / 8; ks++) {
            int kb = ks * 8;
            uint32_t a[4][4];
#pragma unroll
            for (int mi = 0; mi < 4; mi++) {
                int rb = wm * 64 + mi * 16;
                a[mi][0] = f2tf32(sa[(rb + g    ) * SMS + kb + tg]);
                a[mi][1] = f2tf32(sa[(rb + g + 8) * SMS + kb + tg]);
                a[mi][2] = f2tf32(sa[(rb + g    ) * SMS + kb + tg + 4]);
                a[mi][3] = f2tf32(sa[(rb + g + 8) * SMS + kb + tg + 4]);
            }
#pragma unroll
            for (int ni = 0; ni < 4; ni++) {
                int nb = wn * 32 + ni * 8 + g;
                uint32_t bg0 = f2tf32(sg[nb * SMS + kb + tg]);
                uint32_t bg1 = f2tf32(sg[nb * SMS + kb + tg + 4]);
                uint32_t bu0 = f2tf32(su[nb * SMS + kb + tg]);
                uint32_t bu1 = f2tf32(su[nb * SMS + kb + tg + 4]);
#pragma unroll
                for (int mi = 0; mi < 4; mi++) {
                    mma_tf32(cg[mi][ni], a[mi][0], a[mi][1], a[mi][2], a[mi][3], bg0, bg1);
                    mma_tf32(cu[mi][ni], a[mi][0], a[mi][1], a[mi][2], a[mi][3], bu0, bu1);
                }
            }
        }
    }

    // epilogue: act = silu(gate) * up
#pragma unroll
    for (int mi = 0; mi < 4; mi++) {
        int rr = wm * 64 + mi * 16 + g;
        int srow0 = t0 + rr;
        int srow1 = srow0 + 8;
        float* row0 = g_act + ((size_t)e * CAP + srow0) * IDIM;
        float* row1 = g_act + ((size_t)e * CAP + srow1) * IDIM;
#pragma unroll
        for (int ni = 0; ni < 4; ni++) {
            int col = i0 + wn * 32 + ni * 8 + tg * 2;
            if (srow0 < cnt) {
                float g0 = cg[mi][ni][0], g1 = cg[mi][ni][1];
                float2 v;
                v.x = (g0 / (1.f + expf(-g0))) * cu[mi][ni][0];
                v.y = (g1 / (1.f + expf(-g1))) * cu[mi][ni][1];
                *(float2*)(row0 + col) = v;
            }
            if (srow1 < cnt) {
                float g2 = cg[mi][ni][2], g3 = cg[mi][ni][3];
                float2 v;
                v.x = (g2 / (1.f + expf(-g2))) * cu[mi][ni][2];
                v.y = (g3 / (1.f + expf(-g3))) * cu[mi][ni][3];
                *(float2*)(row1 + col) = v;
            }
        }
    }
}

// ---------------- grouped down tf32 GEMM, big warp tiles ----------------
// Block tile: 128 slots x 256 H, BK=16. 8 warps (2x4). Warp tile 64x64.
#define DN_BM 128
#define DN_BN 256
#define DN_BK 16
#define DN_IT (IDIM / DN_BK)
#define DN_A_ST (DN_BM * SMS)                // 2560
#define DN_B_ST (DN_BN * SMS)                // 5120
#define DN_SMEM_BYTES ((NSTG * (DN_A_ST + DN_B_ST)) * 4 + DN_BM * 8)

__global__ __launch_bounds__(256, 1) void down_kernel(const float* __restrict__ dw) {
    int e = blockIdx.z;
    int cnt = g_cnt[e];
    int s0 = blockIdx.y * DN_BM;
    if (s0 >= cnt) return;
    int h0 = blockIdx.x * DN_BN;

    extern __shared__ float dsm[];
    float* SA = dsm;                             // [NSTG][128][SMS]
    float* SB = SA + NSTG * DN_A_ST;             // [NSTG][256][SMS]
    float* wts = SB + NSTG * DN_B_ST;            // [DN_BM]
    int*   dsts = (int*)(wts + DN_BM);           // [DN_BM]

    int tid  = threadIdx.x;
    int lane = tid & 31;
    int warp = tid >> 5;
    int wm = warp >> 2;      // 0..1  (64 rows)
    int wn = warp & 3;       // 0..3  (64 cols)
    int g = lane >> 2;
    int tg = lane & 3;

    if (tid < DN_BM) {
        int s = s0 + tid;
        int cs = (s < cnt) ? s : 0;
        wts[tid]  = g_wt [e * CAP + cs];
        dsts[tid] = g_dst[e * CAP + cs];
    }
    __syncthreads();

    int r0 = tid >> 1;            // 0..127
    int ch = (tid & 1) * 8;       // 0 or 8

    const float* aP  = g_act + ((size_t)e * CAP + s0 + r0) * IDIM + ch;
    const float* bP0 = dw + (size_t)e * H * IDIM + (size_t)(h0 + r0) * IDIM + ch;
    const float* bP1 = bP0 + (size_t)128 * IDIM;

    float acc[4][8][4] = {};

#pragma unroll
    for (int s = 0; s < NSTG - 1; s++) {
        int ko = s * DN_BK;
        float* sa = SA + s * DN_A_ST + r0 * SMS + ch;
        float* sb0 = SB + s * DN_B_ST + r0 * SMS + ch;
        float* sb1 = sb0 + 128 * SMS;
        cp_async16(sa,      aP + ko);
        cp_async16(sa + 4,  aP + ko + 4);
        cp_async16(sb0,     bP0 + ko);
        cp_async16(sb0 + 4, bP0 + ko + 4);
        cp_async16(sb1,     bP1 + ko);
        cp_async16(sb1 + 4, bP1 + ko + 4);
        CP_COMMIT();
    }

    for (int k = 0; k < DN_IT; k++) {
        CP_WAIT2();
        __syncthreads();

        int kn = k + NSTG - 1;
        if (kn < DN_IT) {
            int st = kn & (NSTG - 1);
            int ko = kn * DN_BK;
            float* sa = SA + st * DN_A_ST + r0 * SMS + ch;
            float* sb0 = SB + st * DN_B_ST + r0 * SMS + ch;
            float* sb1 = sb0 + 128 * SMS;
            cp_async16(sa,      aP + ko);
            cp_async16(sa + 4,  aP + ko + 4);
            cp_async16(sb0,     bP0 + ko);
            cp_async16(sb0 + 4, bP0 + ko + 4);
            cp_async16(sb1,     bP1 + ko);
            cp_async16(sb1 + 4, bP1 + ko + 4);
        }
        CP_COMMIT();

        int st = k & (NSTG - 1);
        const float* sa = SA + st * DN_A_ST;
        const float* sb = SB + st * DN_B_ST;
#pragma unroll
        for (int ks = 0; ks < DN_BK / 8; ks++) {
            int kb = ks * 8;
            uint32_t a[4][4];
#pragma unroll
            for (int mi = 0; mi < 4; mi++) {
                int rb = wm * 64 + mi * 16;
                a[mi][0] = f2tf32(sa[(rb + g    ) * SMS + kb + tg]);
                a[mi][1] = f2tf32(sa[(rb + g + 8) * SMS + kb + tg]);
                a[mi][2] = f2tf32(sa[(rb + g    ) * SMS + kb + tg + 4]);
                a[mi][3] = f2tf32(sa[(rb + g + 8) * SMS + kb + tg + 4]);
            }
#pragma unroll
            for (int ni = 0; ni < 8; ni++) {
                int nb = wn * 64 + ni * 8 + g;
                uint32_t b0 = f2tf32(sb[nb * SMS + kb + tg]);
                uint32_t b1 = f2tf32(sb[nb * SMS + kb + tg + 4]);
#pragma unroll
                for (int mi = 0; mi < 4; mi++)
                    mma_tf32(acc[mi][ni], a[mi][0], a[mi][1], a[mi][2], a[mi][3], b0, b1);
            }
        }
    }

#pragma unroll
    for (int mi = 0; mi < 4; mi++) {
        int rr0 = wm * 64 + mi * 16 + g;
        int rr1 = rr0 + 8;
        int srow0 = s0 + rr0;
        int srow1 = s0 + rr1;
        float w0 = wts[rr0], w1 = wts[rr1];
        float* o0 = g_pair + (size_t)dsts[rr0] * H + h0;
        float* o1 = g_pair + (size_t)dsts[rr1] * H + h0;
#pragma unroll
        for (int ni = 0; ni < 8; ni++) {
            int col = wn * 64 + ni * 8 + tg * 2;
            if (srow0 < cnt) {
                float2 v = { acc[mi][ni][0] * w0, acc[mi][ni][1] * w0 };
                *(float2*)(o0 + col) = v;
            }
            if (srow1 < cnt) {
                float2 v = { acc[mi][ni][2] * w1, acc[mi][ni][3] * w1 };
                *(float2*)(o1 + col) = v;
            }
        }
    }
}

// ---------------- combine: out = x*zero_w + valid pair contributions ----------------
__global__ void combine_kernel(const float* __restrict__ x, float* __restrict__ out) {
    int idx = blockIdx.x * blockDim.x + threadIdx.x;
    if (idx >= T_TOK * (H / 4)) return;
    int t  = idx / (H / 4);
    int h4 = idx % (H / 4);
    float4 xv = ((const float4*)x)[idx];
    float zw = g_zw[t];
    int mask = g_mask[t];
    float4 r;
    r.x = xv.x * zw; r.y = xv.y * zw; r.z = xv.z * zw; r.w = xv.w * zw;
    if (mask & 1) {
        float4 p = ((const float4*)(g_pair + (size_t)(t * 2) * H))[h4];
        r.x += p.x; r.y += p.y; r.z += p.z; r.w += p.w;
    }
    if (mask & 2) {
        float4 p = ((const float4*)(g_pair + (size_t)(t * 2 + 1) * H))[h4];
        r.x += p.x; r.y += p.y; r.z += p.z; r.w += p.w;
    }
    ((float4*)out)[idx] = r;
}

// ---------------- launch ----------------
extern "C" void kernel_launch(void* const* d_in, const int* in_sizes, int n_in,
                              void* d_out, int out_size) {
    const float* x    = (const float*)d_in[0];
    const float* cw   = (const float*)d_in[1];
    const float* bias = (const float*)d_in[2];
    const float* gw   = (const float*)d_in[3];
    const float* uw   = (const float*)d_in[4];
    const float* dw   = (const float*)d_in[5];
    float* out = (float*)d_out;

    cudaFuncSetAttribute(gateup_kernel, cudaFuncAttributeMaxDynamicSharedMemorySize, GU_SMEM_BYTES);
    cudaFuncSetAttribute(down_kernel,   cudaFuncAttributeMaxDynamicSharedMemorySize, DN_SMEM_BYTES);

    void* cntAddr = nullptr;
    cudaGetSymbolAddress(&cntAddr, g_cnt);
    cudaMemsetAsync(cntAddr, 0, NE * sizeof(int));

    router_kernel<<<T_TOK / 4, 128>>>(x, cw, bias);

    dim3 gb(IDIM / GU_BN, T_TOK / GU_BM, NE);
    gateup_kernel<<<gb, 256, GU_SMEM_BYTES>>>(x, gw, uw);

    dim3 gd(H / DN_BN, T_TOK / DN_BM, NE);
    down_kernel<<<gd, 256, DN_SMEM_BYTES>>>(dw);

    int n4 = T_TOK * (H / 4);
    combine_kernel<<<(n4 + 255) / 256, 256>>>(x, out);
}

// round 10
// speedup vs baseline: 1.0092x; 1.0092x over previous
#include <cuda_runtime.h>
#include <math.h>
#include <stdint.h>

#define T_TOK 4096
#define H     2048
#define IDIM  1024
#define NE    8
#define NTOT  12
#define CAP   4096
#define SCALE 1.5f

// ---------------- scratch (static device globals; no runtime allocation) ----------------
__device__ int   g_cnt[NE];
__device__ int   g_tok[NE * CAP];
__device__ float g_wt [NE * CAP];
__device__ int   g_dst[NE * CAP];
__device__ float g_zw [T_TOK];
__device__ int   g_mask[T_TOK];
__device__ float g_act [(size_t)NE * CAP * IDIM];     // expert-grouped activations
__device__ float g_pair[(size_t)T_TOK * 2 * H];       // per (token,k) down output

// ---------------- helpers ----------------
__device__ __forceinline__ void cp_async16(void* smem, const void* gmem) {
    uint32_t s = (uint32_t)__cvta_generic_to_shared(smem);
    asm volatile("cp.async.cg.shared.global [%0], [%1], 16;" :: "r"(s), "l"(gmem));
}
#define CP_COMMIT() asm volatile("cp.async.commit_group;")
#define CP_WAIT0()  asm volatile("cp.async.wait_group 0;")

// Raw fp32 bits fed as tf32 (hardware truncates mantissa) — same numerics as R7.
__device__ __forceinline__ void mma_tf32(float c[4],
                                         uint32_t a0, uint32_t a1, uint32_t a2, uint32_t a3,
                                         uint32_t b0, uint32_t b1) {
    asm volatile(
        "mma.sync.aligned.m16n8k8.row.col.f32.tf32.tf32.f32 "
        "{%0,%1,%2,%3}, {%4,%5,%6,%7}, {%8,%9}, {%0,%1,%2,%3};\n"
        : "+f"(c[0]), "+f"(c[1]), "+f"(c[2]), "+f"(c[3])
        : "r"(a0), "r"(a1), "r"(a2), "r"(a3), "r"(b0), "r"(b1));
}

// ---------------- router: one warp per token ----------------
__global__ void router_kernel(const float* __restrict__ x,
                              const float* __restrict__ cw,
                              const float* __restrict__ bias) {
    int warp = threadIdx.x >> 5;
    int lane = threadIdx.x & 31;
    int t = blockIdx.x * 4 + warp;
    if (t >= T_TOK) return;
    const float* xr = x + (size_t)t * H;

    float acc[NTOT];
#pragma unroll
    for (int e = 0; e < NTOT; e++) acc[e] = 0.f;
    for (int h = lane; h < H; h += 32) {
        float xv = xr[h];
#pragma unroll
        for (int e = 0; e < NTOT; e++) acc[e] += xv * __ldg(&cw[e * H + h]);
    }
#pragma unroll
    for (int e = 0; e < NTOT; e++) {
#pragma unroll
        for (int off = 16; off; off >>= 1)
            acc[e] += __shfl_xor_sync(0xffffffffu, acc[e], off);
    }
    if (lane == 0) {
        float m = acc[0];
#pragma unroll
        for (int e = 1; e < NTOT; e++) m = fmaxf(m, acc[e]);
        float p[NTOT];
        float s = 0.f;
#pragma unroll
        for (int e = 0; e < NTOT; e++) { p[e] = expf(acc[e] - m); s += p[e]; }
        float inv = 1.f / s;
        float biased[NTOT];
#pragma unroll
        for (int e = 0; e < NTOT; e++) { p[e] *= inv; biased[e] = p[e] + bias[e]; }

        // top-2 of biased scores (lowest index wins ties, matching jax.lax.top_k)
        int i0 = 0;
#pragma unroll
        for (int e = 1; e < NTOT; e++) if (biased[e] > biased[i0]) i0 = e;
        int i1 = (i0 == 0) ? 1 : 0;
#pragma unroll
        for (int e = 0; e < NTOT; e++)
            if (e != i0 && biased[e] > biased[i1]) i1 = e;

        int sel[2] = { i0, i1 };
        float zw = 0.f;
        int mask = 0;
#pragma unroll
        for (int k = 0; k < 2; k++) {
            int e = sel[k];
            float w = p[e] * SCALE;       // weight uses UNBIASED prob
            if (e < NE) {
                int slot = atomicAdd(&g_cnt[e], 1);
                g_tok[e * CAP + slot] = t;
                g_wt [e * CAP + slot] = w;
                g_dst[e * CAP + slot] = t * 2 + k;
                mask |= (1 << k);
            } else {
                zw += w;
            }
        }
        g_zw[t]  = zw;
        g_mask[t] = mask;
    }
}

// ---------------- grouped gate+up tf32 GEMM, BK=32, 2-stage cp.async ----------------
// Block tile: 128 slots x 64 inter. 8 warps (4x2). Warp tile 32x32 for BOTH
// gate and up (shared A fragments). Grid: token-tile fastest (L2 weight reuse).
#define GU_BM 128
#define GU_BN 64
#define GU_BK 32
#define GU_IT (H / GU_BK)
#define SMS 36          // k-stride (32 + 4 pad) -> conflict-free fragment LDS
#define GU_A_ST (GU_BM * SMS)                  // 4608 floats
#define GU_B_ST (GU_BN * SMS)                  // 2304 floats
#define GU_STAGE (GU_A_ST + 2 * GU_B_ST)       // 9216 floats per stage
#define GU_SMEM_BYTES (2 * GU_STAGE * 4 + GU_BM * 4)

__global__ __launch_bounds__(256, 2) void gateup_kernel(const float* __restrict__ x,
                                                        const float* __restrict__ gw,
                                                        const float* __restrict__ uw) {
    int e = blockIdx.z;
    int cnt = g_cnt[e];
    int t0 = blockIdx.x * GU_BM;       // token-tile = fastest dim
    if (t0 >= cnt) return;
    int i0 = blockIdx.y * GU_BN;

    extern __shared__ float dsm[];
    int*   toks = (int*)(dsm + 2 * GU_STAGE);

    int tid  = threadIdx.x;
    int lane = tid & 31;
    int warp = tid >> 5;
    int wm = warp >> 1;       // 0..3
    int wn = warp & 1;        // 0..1
    int g = lane >> 2;        // 0..7
    int tg = lane & 3;        // 0..3

    if (tid < GU_BM) {
        int s = t0 + tid;
        toks[tid] = g_tok[e * CAP + ((s < cnt) ? s : 0)];
    }
    __syncthreads();

    // staging: A 2 thr/row x 16 floats; G/U 4 thr/row x 8 floats
    int rA = tid >> 1;              // 0..127
    int cA = (tid & 1) * 16;        // 0 or 16
    int rB = tid >> 2;              // 0..63
    int cB = (tid & 3) * 8;         // 0,8,16,24

    const float* aP = x + (size_t)toks[rA] * H + cA;
    const float* gP = gw + (size_t)e * IDIM * H + (size_t)(i0 + rB) * H + cB;
    const float* uP = uw + (size_t)e * IDIM * H + (size_t)(i0 + rB) * H + cB;

    float cg[2][4][4] = {};
    float cu[2][4][4] = {};

    // prologue: chunk 0 -> stage 0
    {
        float* sa = dsm + rA * SMS + cA;
        float* sg = dsm + GU_A_ST + rB * SMS + cB;
        float* su = dsm + GU_A_ST + GU_B_ST + rB * SMS + cB;
#pragma unroll
        for (int j = 0; j < 4; j++) cp_async16(sa + j * 4, aP + j * 4);
        cp_async16(sg, gP); cp_async16(sg + 4, gP + 4);
        cp_async16(su, uP); cp_async16(su + 4, uP + 4);
    }
    CP_COMMIT();

    for (int k = 0; k < GU_IT; k++) {
        CP_WAIT0();
        __syncthreads();          // chunk k visible; stage (k+1)&1 free

        int kn = k + 1;
        if (kn < GU_IT) {
            int ko = kn * GU_BK;
            float* base = dsm + (kn & 1) * GU_STAGE;
            float* sa = base + rA * SMS + cA;
            float* sg = base + GU_A_ST + rB * SMS + cB;
            float* su = base + GU_A_ST + GU_B_ST + rB * SMS + cB;
#pragma unroll
            for (int j = 0; j < 4; j++) cp_async16(sa + j * 4, aP + ko + j * 4);
            cp_async16(sg, gP + ko); cp_async16(sg + 4, gP + ko + 4);
            cp_async16(su, uP + ko); cp_async16(su + 4, uP + ko + 4);
        }
        CP_COMMIT();

        const float* base = dsm + (k & 1) * GU_STAGE;
        const float* sa = base;
        const float* sg = base + GU_A_ST;
        const float* su = base + GU_A_ST + GU_B_ST;
#pragma unroll
        for (int ks = 0; ks < GU_BK / 8; ks++) {
            int kb = ks * 8;
            uint32_t a[2][4];
#pragma unroll
            for (int mi = 0; mi < 2; mi++) {
                int rb = wm * 32 + mi * 16;
                a[mi][0] = __float_as_uint(sa[(rb + g    ) * SMS + kb + tg]);
                a[mi][1] = __float_as_uint(sa[(rb + g + 8) * SMS + kb + tg]);
                a[mi][2] = __float_as_uint(sa[(rb + g    ) * SMS + kb + tg + 4]);
                a[mi][3] = __float_as_uint(sa[(rb + g + 8) * SMS + kb + tg + 4]);
            }
#pragma unroll
            for (int ni = 0; ni < 4; ni++) {
                int nb = wn * 32 + ni * 8 + g;
                uint32_t bg0 = __float_as_uint(sg[nb * SMS + kb + tg]);
                uint32_t bg1 = __float_as_uint(sg[nb * SMS + kb + tg + 4]);
                uint32_t bu0 = __float_as_uint(su[nb * SMS + kb + tg]);
                uint32_t bu1 = __float_as_uint(su[nb * SMS + kb + tg + 4]);
#pragma unroll
                for (int mi = 0; mi < 2; mi++) {
                    mma_tf32(cg[mi][ni], a[mi][0], a[mi][1], a[mi][2], a[mi][3], bg0, bg1);
                    mma_tf32(cu[mi][ni], a[mi][0], a[mi][1], a[mi][2], a[mi][3], bu0, bu1);
                }
            }
        }
    }

    // epilogue: act = silu(gate) * up
#pragma unroll
    for (int mi = 0; mi < 2; mi++) {
        int rr = wm * 32 + mi * 16 + g;
        int srow0 = t0 + rr;
        int srow1 = srow0 + 8;
        float* row0 = g_act + ((size_t)e * CAP + srow0) * IDIM;
        float* row1 = g_act + ((size_t)e * CAP + srow1) * IDIM;
#pragma unroll
        for (int ni = 0; ni < 4; ni++) {
            int col = i0 + wn * 32 + ni * 8 + tg * 2;
            if (srow0 < cnt) {
                float g0 = cg[mi][ni][0], g1 = cg[mi][ni][1];
                float2 v;
                v.x = (g0 / (1.f + expf(-g0))) * cu[mi][ni][0];
                v.y = (g1 / (1.f + expf(-g1))) * cu[mi][ni][1];
                *(float2*)(row0 + col) = v;
            }
            if (srow1 < cnt) {
                float g2 = cg[mi][ni][2], g3 = cg[mi][ni][3];
                float2 v;
                v.x = (g2 / (1.f + expf(-g2))) * cu[mi][ni][2];
                v.y = (g3 / (1.f + expf(-g3))) * cu[mi][ni][3];
                *(float2*)(row1 + col) = v;
            }
        }
    }
}

// ---------------- grouped down tf32 GEMM, BK=32, 2-stage cp.async ----------------
// Block tile: 128 slots x 128 H. 8 warps (4x2). Warp tile 32x64.
#define DN_BM 128
#define DN_BN 128
#define DN_BK 32
#define DN_IT (IDIM / DN_BK)
#define DN_T_ST (DN_BM * SMS)                  // 4608 floats (A or B)
#define DN_STAGE (2 * DN_T_ST)                 // 9216 floats
#define DN_SMEM_BYTES (2 * DN_STAGE * 4 + DN_BM * 8)

__global__ __launch_bounds__(256, 2) void down_kernel(const float* __restrict__ dw) {
    int e = blockIdx.z;
    int cnt = g_cnt[e];
    int s0 = blockIdx.x * DN_BM;       // slot-tile = fastest dim
    if (s0 >= cnt) return;
    int h0 = blockIdx.y * DN_BN;

    extern __shared__ float dsm[];
    float* wts = dsm + 2 * DN_STAGE;            // [DN_BM]
    int*   dsts = (int*)(wts + DN_BM);          // [DN_BM]

    int tid  = threadIdx.x;
    int lane = tid & 31;
    int warp = tid >> 5;
    int wm = warp >> 1;      // 0..3
    int wn = warp & 1;       // 0..1
    int g = lane >> 2;
    int tg = lane & 3;

    if (tid < DN_BM) {
        int s = s0 + tid;
        int cs = (s < cnt) ? s : 0;
        wts[tid]  = g_wt [e * CAP + cs];
        dsts[tid] = g_dst[e * CAP + cs];
    }
    __syncthreads();

    int r0 = tid >> 1;            // 0..127
    int ch = (tid & 1) * 16;      // 0 or 16

    const float* aP = g_act + ((size_t)e * CAP + s0 + r0) * IDIM + ch;
    const float* bP = dw + (size_t)e * H * IDIM + (size_t)(h0 + r0) * IDIM + ch;

    float acc[2][8][4] = {};

    {
        float* sa = dsm + r0 * SMS + ch;
        float* sb = dsm + DN_T_ST + r0 * SMS + ch;
#pragma unroll
        for (int j = 0; j < 4; j++) {
            cp_async16(sa + j * 4, aP + j * 4);
            cp_async16(sb + j * 4, bP + j * 4);
        }
    }
    CP_COMMIT();

    for (int k = 0; k < DN_IT; k++) {
        CP_WAIT0();
        __syncthreads();

        int kn = k + 1;
        if (kn < DN_IT) {
            int ko = kn * DN_BK;
            float* base = dsm + (kn & 1) * DN_STAGE;
            float* sa = base + r0 * SMS + ch;
            float* sb = base + DN_T_ST + r0 * SMS + ch;
#pragma unroll
            for (int j = 0; j < 4; j++) {
                cp_async16(sa + j * 4, aP + ko + j * 4);
                cp_async16(sb + j * 4, bP + ko + j * 4);
            }
        }
        CP_COMMIT();

        const float* base = dsm + (k & 1) * DN_STAGE;
        const float* sa = base;
        const float* sb = base + DN_T_ST;
#pragma unroll
        for (int ks = 0; ks < DN_BK / 8; ks++) {
            int kb = ks * 8;
            uint32_t a[2][4];
#pragma unroll
            for (int mi = 0; mi < 2; mi++) {
                int rb = wm * 32 + mi * 16;
                a[mi][0] = __float_as_uint(sa[(rb + g    ) * SMS + kb + tg]);
                a[mi][1] = __float_as_uint(sa[(rb + g + 8) * SMS + kb + tg]);
                a[mi][2] = __float_as_uint(sa[(rb + g    ) * SMS + kb + tg + 4]);
                a[mi][3] = __float_as_uint(sa[(rb + g + 8) * SMS + kb + tg + 4]);
            }
#pragma unroll
            for (int ni = 0; ni < 8; ni++) {
                int nb = wn * 64 + ni * 8 + g;
                uint32_t b0 = __float_as_uint(sb[nb * SMS + kb + tg]);
                uint32_t b1 = __float_as_uint(sb[nb * SMS + kb + tg + 4]);
#pragma unroll
                for (int mi = 0; mi < 2; mi++)
                    mma_tf32(acc[mi][ni], a[mi][0], a[mi][1], a[mi][2], a[mi][3], b0, b1);
            }
        }
    }

#pragma unroll
    for (int mi = 0; mi < 2; mi++) {
        int rr0 = wm * 32 + mi * 16 + g;
        int rr1 = rr0 + 8;
        int srow0 = s0 + rr0;
        int srow1 = s0 + rr1;
        float w0 = wts[rr0], w1 = wts[rr1];
        float* o0 = g_pair + (size_t)dsts[rr0] * H + h0;
        float* o1 = g_pair + (size_t)dsts[rr1] * H + h0;
#pragma unroll
        for (int ni = 0; ni < 8; ni++) {
            int col = wn * 64 + ni * 8 + tg * 2;
            if (srow0 < cnt) {
                float2 v = { acc[mi][ni][0] * w0, acc[mi][ni][1] * w0 };
                *(float2*)(o0 + col) = v;
            }
            if (srow1 < cnt) {
                float2 v = { acc[mi][ni][2] * w1, acc[mi][ni][3] * w1 };
                *(float2*)(o1 + col) = v;
            }
        }
    }
}

// ---------------- combine: out = x*zero_w + valid pair contributions ----------------
__global__ void combine_kernel(const float* __restrict__ x, float* __restrict__ out) {
    int idx = blockIdx.x * blockDim.x + threadIdx.x;
    if (idx >= T_TOK * (H / 4)) return;
    int t  = idx / (H / 4);
    int h4 = idx % (H / 4);
    float4 xv = ((const float4*)x)[idx];
    float zw = g_zw[t];
    int mask = g_mask[t];
    float4 r;
    r.x = xv.x * zw; r.y = xv.y * zw; r.z = xv.z * zw; r.w = xv.w * zw;
    if (mask & 1) {
        float4 p = ((const float4*)(g_pair + (size_t)(t * 2) * H))[h4];
        r.x += p.x; r.y += p.y; r.z += p.z; r.w += p.w;
    }
    if (mask & 2) {
        float4 p = ((const float4*)(g_pair + (size_t)(t * 2 + 1) * H))[h4];
        r.x += p.x; r.y += p.y; r.z += p.z; r.w += p.w;
    }
    ((float4*)out)[idx] = r;
}

// ---------------- launch ----------------
extern "C" void kernel_launch(void* const* d_in, const int* in_sizes, int n_in,
                              void* d_out, int out_size) {
    const float* x    = (const float*)d_in[0];
    const float* cw   = (const float*)d_in[1];
    const float* bias = (const float*)d_in[2];
    const float* gw   = (const float*)d_in[3];
    const float* uw   = (const float*)d_in[4];
    const float* dw   = (const float*)d_in[5];
    float* out = (float*)d_out;

    cudaFuncSetAttribute(gateup_kernel, cudaFuncAttributeMaxDynamicSharedMemorySize, GU_SMEM_BYTES);
    cudaFuncSetAttribute(down_kernel,   cudaFuncAttributeMaxDynamicSharedMemorySize, DN_SMEM_BYTES);

    void* cntAddr = nullptr;
    cudaGetSymbolAddress(&cntAddr, g_cnt);
    cudaMemsetAsync(cntAddr, 0, NE * sizeof(int));

    router_kernel<<<T_TOK / 4, 128>>>(x, cw, bias);

    // token-tile fastest -> consecutive blocks share the same weight slab (L2 reuse)
    dim3 gb(T_TOK / GU_BM, IDIM / GU_BN, NE);
    gateup_kernel<<<gb, 256, GU_SMEM_BYTES>>>(x, gw, uw);

    dim3 gd(T_TOK / DN_BM, H / DN_BN, NE);
    down_kernel<<<gd, 256, DN_SMEM_BYTES>>>(dw);

    int n4 = T_TOK * (H / 4);
    combine_kernel<<<(n4 + 255) / 256, 256>>>(x, out);
}

// round 12
// speedup vs baseline: 1.9356x; 1.9179x over previous
#include <cuda_runtime.h>
#include <cuda_fp16.h>
#include <math.h>
#include <stdint.h>

#define T_TOK 4096
#define H     2048
#define IDIM  1024
#define NE    8
#define NTOT  12
#define CAP   4096
#define SCALE 1.5f

// ---------------- scratch (static device globals; no runtime allocation) ----------------
__device__ int   g_cnt[NE];
__device__ int   g_tok[NE * CAP];
__device__ float g_wt [NE * CAP];
__device__ int   g_dst[NE * CAP];
__device__ float g_zw [T_TOK];
__device__ int   g_mask[T_TOK];
__device__ __half g_hx [(size_t)T_TOK * H];           // fp16 hidden states
__device__ __half g_hgw[(size_t)NE * IDIM * H];       // fp16 gate weights
__device__ __half g_huw[(size_t)NE * IDIM * H];       // fp16 up weights
__device__ __half g_hdw[(size_t)NE * H * IDIM];       // fp16 down weights
__device__ __half g_act[(size_t)NE * CAP * IDIM];     // fp16 expert-grouped activations
__device__ float g_pair[(size_t)T_TOK * 2 * H];       // per (token,k) down output (fp32)

// ---------------- helpers ----------------
__device__ __forceinline__ void cp_async16(void* smem, const void* gmem) {
    uint32_t s = (uint32_t)__cvta_generic_to_shared(smem);
    asm volatile("cp.async.cg.shared.global [%0], [%1], 16;" :: "r"(s), "l"(gmem));
}
#define CP_COMMIT() asm volatile("cp.async.commit_group;")
#define CP_WAIT0()  asm volatile("cp.async.wait_group 0;")

__device__ __forceinline__ uint32_t smem_u32(const void* p) {
    return (uint32_t)__cvta_generic_to_shared(p);
}

__device__ __forceinline__ uint32_t pack2(float a, float b) {
    __half2 h = __floats2half2_rn(a, b);
    return *reinterpret_cast<uint32_t*>(&h);
}

#define LDSM_X4(r0, r1, r2, r3, addr) \
    asm volatile("ldmatrix.sync.aligned.m8n8.x4.shared.b16 {%0,%1,%2,%3}, [%4];" \
                 : "=r"(r0), "=r"(r1), "=r"(r2), "=r"(r3) : "r"(addr))

__device__ __forceinline__ void mma_f16(float c[4],
                                        uint32_t a0, uint32_t a1, uint32_t a2, uint32_t a3,
                                        uint32_t b0, uint32_t b1) {
    asm volatile(
        "mma.sync.aligned.m16n8k16.row.col.f32.f16.f16.f32 "
        "{%0,%1,%2,%3}, {%4,%5,%6,%7}, {%8,%9}, {%0,%1,%2,%3};\n"
        : "+f"(c[0]), "+f"(c[1]), "+f"(c[2]), "+f"(c[3])
        : "r"(a0), "r"(a1), "r"(a2), "r"(a3), "r"(b0), "r"(b1));
}

// ---------------- fp32 -> fp16 conversion (16B granules) ----------------
__global__ void cvt_kernel(const float* __restrict__ src, __half* __restrict__ dst, int n8) {
    int i = blockIdx.x * blockDim.x + threadIdx.x;   // one per 8 elements
    if (i >= n8) return;
    const float4* s4 = (const float4*)src + (size_t)i * 2;
    float4 a = s4[0], b = s4[1];
    uint4 o;
    o.x = pack2(a.x, a.y); o.y = pack2(a.z, a.w);
    o.z = pack2(b.x, b.y); o.w = pack2(b.z, b.w);
    ((uint4*)dst)[i] = o;
}

// ---------------- router: one warp per token (fp32 — exact expert selection) ----------------
__global__ void router_kernel(const float* __restrict__ x,
                              const float* __restrict__ cw,
                              const float* __restrict__ bias) {
    int warp = threadIdx.x >> 5;
    int lane = threadIdx.x & 31;
    int t = blockIdx.x * 4 + warp;
    if (t >= T_TOK) return;
    const float* xr = x + (size_t)t * H;

    float acc[NTOT];
#pragma unroll
    for (int e = 0; e < NTOT; e++) acc[e] = 0.f;
    for (int h = lane; h < H; h += 32) {
        float xv = xr[h];
#pragma unroll
        for (int e = 0; e < NTOT; e++) acc[e] += xv * __ldg(&cw[e * H + h]);
    }
#pragma unroll
    for (int e = 0; e < NTOT; e++) {
#pragma unroll
        for (int off = 16; off; off >>= 1)
            acc[e] += __shfl_xor_sync(0xffffffffu, acc[e], off);
    }
    if (lane == 0) {
        float m = acc[0];
#pragma unroll
        for (int e = 1; e < NTOT; e++) m = fmaxf(m, acc[e]);
        float p[NTOT];
        float s = 0.f;
#pragma unroll
        for (int e = 0; e < NTOT; e++) { p[e] = expf(acc[e] - m); s += p[e]; }
        float inv = 1.f / s;
        float biased[NTOT];
#pragma unroll
        for (int e = 0; e < NTOT; e++) { p[e] *= inv; biased[e] = p[e] + bias[e]; }

        // top-2 of biased scores (lowest index wins ties, matching jax.lax.top_k)
        int i0 = 0;
#pragma unroll
        for (int e = 1; e < NTOT; e++) if (biased[e] > biased[i0]) i0 = e;
        int i1 = (i0 == 0) ? 1 : 0;
#pragma unroll
        for (int e = 0; e < NTOT; e++)
            if (e != i0 && biased[e] > biased[i1]) i1 = e;

        int sel[2] = { i0, i1 };
        float zw = 0.f;
        int mask = 0;
#pragma unroll
        for (int k = 0; k < 2; k++) {
            int e = sel[k];
            float w = p[e] * SCALE;       // weight uses UNBIASED prob
            if (e < NE) {
                int slot = atomicAdd(&g_cnt[e], 1);
                g_tok[e * CAP + slot] = t;
                g_wt [e * CAP + slot] = w;
                g_dst[e * CAP + slot] = t * 2 + k;
                mask |= (1 << k);
            } else {
                zw += w;
            }
        }
        g_zw[t]  = zw;
        g_mask[t] = mask;
    }
}

// ---------------- gateup fp16 GEMM (ldmatrix + m16n8k16), fused SiLU ----------------
// Block tile: 128 slots x 64 inter, BK=32 halves. 8 warps (4x2). Warp 32x32 both mats.
#define GU_BM 128
#define GU_BN 64
#define GU_BK 32
#define GU_IT (H / GU_BK)     // 64
#define SMSH 40               // smem row stride (halves): 80B -> conflict-free ldmatrix

__global__ __launch_bounds__(256, 2) void gateup_kernel() {
    int e = blockIdx.z;
    int cnt = g_cnt[e];
    int t0 = blockIdx.y * GU_BM;
    if (t0 >= cnt) return;
    int i0 = blockIdx.x * GU_BN;

    __shared__ __half SA[2][GU_BM * SMSH];
    __shared__ __half SG[2][GU_BN * SMSH];
    __shared__ __half SU[2][GU_BN * SMSH];
    __shared__ int toks[GU_BM];

    int tid  = threadIdx.x;
    int lane = tid & 31;
    int warp = tid >> 5;
    int wm = warp >> 1;       // 0..3 (m 32 rows each)
    int wn = warp & 1;        // 0..1 (n 32 cols each)

    if (tid < GU_BM) {
        int s = t0 + tid;
        toks[tid] = g_tok[e * CAP + ((s < cnt) ? s : 0)];
    }
    __syncthreads();

    const __half* gw_e = g_hgw + (size_t)e * IDIM * H + (size_t)i0 * H;
    const __half* uw_e = g_huw + (size_t)e * IDIM * H + (size_t)i0 * H;

    // staging coords
    int rS = tid >> 2;            // 0..63
    int cS = (tid & 3) * 8;       // chunk in halves (16B)

    // fragment offsets (bytes) within a stage
    uint32_t saB[2] = { smem_u32(&SA[0][0]), smem_u32(&SA[1][0]) };
    uint32_t sgB[2] = { smem_u32(&SG[0][0]), smem_u32(&SG[1][0]) };
    uint32_t suB[2] = { smem_u32(&SU[0][0]), smem_u32(&SU[1][0]) };
    uint32_t offA[2], offB[2];
#pragma unroll
    for (int mi = 0; mi < 2; mi++)
        offA[mi] = ((wm * 32 + mi * 16 + (lane & 15)) * SMSH + (lane >> 4) * 8) * 2;
#pragma unroll
    for (int nt = 0; nt < 2; nt++)
        offB[nt] = ((wn * 32 + nt * 16 + (lane & 7) + ((lane >> 4) << 3)) * SMSH
                    + ((lane >> 3) & 1) * 8) * 2;

    float cg[2][4][4] = {};
    float cu[2][4][4] = {};

    auto fill = [&](int st, int k0) {
#pragma unroll
        for (int p = 0; p < 2; p++) {
            int r = rS + p * 64;
            cp_async16(&SA[st][r * SMSH + cS], g_hx + (size_t)toks[r] * H + k0 + cS);
        }
        cp_async16(&SG[st][rS * SMSH + cS], gw_e + (size_t)rS * H + k0 + cS);
        cp_async16(&SU[st][rS * SMSH + cS], uw_e + (size_t)rS * H + k0 + cS);
    };

    fill(0, 0); CP_COMMIT();

    for (int k = 0; k < GU_IT; k++) {
        CP_WAIT0();
        __syncthreads();

        int kn = k + 1;
        if (kn < GU_IT) fill(kn & 1, kn * GU_BK);
        CP_COMMIT();

        int st = k & 1;
#pragma unroll
        for (int ks = 0; ks < 2; ks++) {
            uint32_t a[2][4];
#pragma unroll
            for (int mi = 0; mi < 2; mi++)
                LDSM_X4(a[mi][0], a[mi][1], a[mi][2], a[mi][3], saB[st] + offA[mi] + ks * 32);
#pragma unroll
            for (int nt = 0; nt < 2; nt++) {
                uint32_t bg[4], bu[4];
                LDSM_X4(bg[0], bg[1], bg[2], bg[3], sgB[st] + offB[nt] + ks * 32);
                LDSM_X4(bu[0], bu[1], bu[2], bu[3], suB[st] + offB[nt] + ks * 32);
#pragma unroll
                for (int h = 0; h < 2; h++) {
                    int ni = nt * 2 + h;
#pragma unroll
                    for (int mi = 0; mi < 2; mi++) {
                        mma_f16(cg[mi][ni], a[mi][0], a[mi][1], a[mi][2], a[mi][3], bg[2 * h], bg[2 * h + 1]);
                        mma_f16(cu[mi][ni], a[mi][0], a[mi][1], a[mi][2], a[mi][3], bu[2 * h], bu[2 * h + 1]);
                    }
                }
            }
        }
    }

    // epilogue: act = silu(gate) * up -> fp16
#pragma unroll
    for (int mi = 0; mi < 2; mi++) {
        int r0 = wm * 32 + mi * 16 + (lane >> 2);
        int srow0 = t0 + r0;
        int srow1 = srow0 + 8;
        __half* row0 = g_act + ((size_t)e * CAP + srow0) * IDIM + i0;
        __half* row1 = g_act + ((size_t)e * CAP + srow1) * IDIM + i0;
#pragma unroll
        for (int ni = 0; ni < 4; ni++) {
            int col = wn * 32 + ni * 8 + (lane & 3) * 2;
            if (srow0 < cnt) {
                float g0 = cg[mi][ni][0], g1 = cg[mi][ni][1];
                float v0 = (g0 / (1.f + expf(-g0))) * cu[mi][ni][0];
                float v1 = (g1 / (1.f + expf(-g1))) * cu[mi][ni][1];
                *(uint32_t*)(row0 + col) = pack2(v0, v1);
            }
            if (srow1 < cnt) {
                float g2 = cg[mi][ni][2], g3 = cg[mi][ni][3];
                float v2 = (g2 / (1.f + expf(-g2))) * cu[mi][ni][2];
                float v3 = (g3 / (1.f + expf(-g3))) * cu[mi][ni][3];
                *(uint32_t*)(row1 + col) = pack2(v2, v3);
            }
        }
    }
}

// ---------------- down fp16 GEMM (ldmatrix + m16n8k16), weight-scaled scatter ----------------
// Block tile: 128 slots x 128 H, BK=32. 8 warps (4x2). Warp 32x64.
#define DN_BM 128
#define DN_BN 128
#define DN_BK 32
#define DN_IT (IDIM / DN_BK)   // 32

__global__ __launch_bounds__(256, 2) void down_kernel() {
    int e = blockIdx.z;
    int cnt = g_cnt[e];
    int s0 = blockIdx.y * DN_BM;
    if (s0 >= cnt) return;
    int h0 = blockIdx.x * DN_BN;

    __shared__ __half SA[2][DN_BM * SMSH];
    __shared__ __half SB[2][DN_BN * SMSH];
    __shared__ float wts[DN_BM];
    __shared__ int dsts[DN_BM];

    int tid  = threadIdx.x;
    int lane = tid & 31;
    int warp = tid >> 5;
    int wm = warp >> 1;      // 0..3
    int wn = warp & 1;       // 0..1 (n 64 each)

    if (tid < DN_BM) {
        int s = s0 + tid;
        int cs = (s < cnt) ? s : 0;
        wts[tid]  = g_wt [e * CAP + cs];
        dsts[tid] = g_dst[e * CAP + cs];
    }
    __syncthreads();

    const __half* aBase = g_act + ((size_t)e * CAP + s0) * IDIM;
    const __half* bBase = g_hdw + (size_t)e * H * IDIM + (size_t)h0 * IDIM;

    int rS = tid >> 2;            // 0..63
    int cS = (tid & 3) * 8;

    uint32_t saB[2] = { smem_u32(&SA[0][0]), smem_u32(&SA[1][0]) };
    uint32_t sbB[2] = { smem_u32(&SB[0][0]), smem_u32(&SB[1][0]) };
    uint32_t offA[2], offB[4];
#pragma unroll
    for (int mi = 0; mi < 2; mi++)
        offA[mi] = ((wm * 32 + mi * 16 + (lane & 15)) * SMSH + (lane >> 4) * 8) * 2;
#pragma unroll
    for (int nt = 0; nt < 4; nt++)
        offB[nt] = ((wn * 64 + nt * 16 + (lane & 7) + ((lane >> 4) << 3)) * SMSH
                    + ((lane >> 3) & 1) * 8) * 2;

    float acc[2][8][4] = {};

    auto fill = [&](int st, int k0) {
#pragma unroll
        for (int p = 0; p < 2; p++) {
            int r = rS + p * 64;
            cp_async16(&SA[st][r * SMSH + cS], aBase + (size_t)r * IDIM + k0 + cS);
            cp_async16(&SB[st][r * SMSH + cS], bBase + (size_t)r * IDIM + k0 + cS);
        }
    };

    fill(0, 0); CP_COMMIT();

    for (int k = 0; k < DN_IT; k++) {
        CP_WAIT0();
        __syncthreads();

        int kn = k + 1;
        if (kn < DN_IT) fill(kn & 1, kn * DN_BK);
        CP_COMMIT();

        int st = k & 1;
#pragma unroll
        for (int ks = 0; ks < 2; ks++) {
            uint32_t a[2][4];
#pragma unroll
            for (int mi = 0; mi < 2; mi++)
                LDSM_X4(a[mi][0], a[mi][1], a[mi][2], a[mi][3], saB[st] + offA[mi] + ks * 32);
#pragma unroll
            for (int nt = 0; nt < 4; nt++) {
                uint32_t b[4];
                LDSM_X4(b[0], b[1], b[2], b[3], sbB[st] + offB[nt] + ks * 32);
#pragma unroll
                for (int h = 0; h < 2; h++) {
                    int ni = nt * 2 + h;
#pragma unroll
                    for (int mi = 0; mi < 2; mi++)
                        mma_f16(acc[mi][ni], a[mi][0], a[mi][1], a[mi][2], a[mi][3], b[2 * h], b[2 * h + 1]);
                }
            }
        }
    }

#pragma unroll
    for (int mi = 0; mi < 2; mi++) {
        int r0 = wm * 32 + mi * 16 + (lane >> 2);
        int r1 = r0 + 8;
        int srow0 = s0 + r0;
        int srow1 = s0 + r1;
        float w0 = wts[r0], w1 = wts[r1];
        float* o0 = g_pair + (size_t)dsts[r0] * H + h0;
        float* o1 = g_pair + (size_t)dsts[r1] * H + h0;
#pragma unroll
        for (int ni = 0; ni < 8; ni++) {
            int col = wn * 64 + ni * 8 + (lane & 3) * 2;
            if (srow0 < cnt) {
                float2 v = { acc[mi][ni][0] * w0, acc[mi][ni][1] * w0 };
                *(float2*)(o0 + col) = v;
            }
            if (srow1 < cnt) {
                float2 v = { acc[mi][ni][2] * w1, acc[mi][ni][3] * w1 };
                *(float2*)(o1 + col) = v;
            }
        }
    }
}

// ---------------- combine: out = x*zero_w + valid pair contributions ----------------
__global__ void combine_kernel(const float* __restrict__ x, float* __restrict__ out) {
    int idx = blockIdx.x * blockDim.x + threadIdx.x;
    if (idx >= T_TOK * (H / 4)) return;
    int t  = idx / (H / 4);
    int h4 = idx % (H / 4);
    float4 xv = ((const float4*)x)[idx];
    float zw = g_zw[t];
    int mask = g_mask[t];
    float4 r;
    r.x = xv.x * zw; r.y = xv.y * zw; r.z = xv.z * zw; r.w = xv.w * zw;
    if (mask & 1) {
        float4 p = ((const float4*)(g_pair + (size_t)(t * 2) * H))[h4];
        r.x += p.x; r.y += p.y; r.z += p.z; r.w += p.w;
    }
    if (mask & 2) {
        float4 p = ((const float4*)(g_pair + (size_t)(t * 2 + 1) * H))[h4];
        r.x += p.x; r.y += p.y; r.z += p.z; r.w += p.w;
    }
    ((float4*)out)[idx] = r;
}

// ---------------- launch ----------------
extern "C" void kernel_launch(void* const* d_in, const int* in_sizes, int n_in,
                              void* d_out, int out_size) {
    const float* x    = (const float*)d_in[0];
    const float* cw   = (const float*)d_in[1];
    const float* bias = (const float*)d_in[2];
    const float* gw   = (const float*)d_in[3];
    const float* uw   = (const float*)d_in[4];
    const float* dw   = (const float*)d_in[5];
    float* out = (float*)d_out;

    void* cntAddr = nullptr;
    cudaGetSymbolAddress(&cntAddr, g_cnt);
    cudaMemsetAsync(cntAddr, 0, NE * sizeof(int));

    // fp32 -> fp16 conversions
    void* p;
    cudaGetSymbolAddress(&p, g_hx);
    { int n8 = T_TOK * H / 8;        cvt_kernel<<<(n8 + 255) / 256, 256>>>(x,  (__half*)p, n8); }
    cudaGetSymbolAddress(&p, g_hgw);
    { int n8 = NE * IDIM * H / 8;    cvt_kernel<<<(n8 + 255) / 256, 256>>>(gw, (__half*)p, n8); }
    cudaGetSymbolAddress(&p, g_huw);
    { int n8 = NE * IDIM * H / 8;    cvt_kernel<<<(n8 + 255) / 256, 256>>>(uw, (__half*)p, n8); }
    cudaGetSymbolAddress(&p, g_hdw);
    { int n8 = NE * H * IDIM / 8;    cvt_kernel<<<(n8 + 255) / 256, 256>>>(dw, (__half*)p, n8); }

    router_kernel<<<T_TOK / 4, 128>>>(x, cw, bias);

    dim3 gb(IDIM / GU_BN, T_TOK / GU_BM, NE);
    gateup_kernel<<<gb, 256>>>();

    dim3 gd(H / DN_BN, T_TOK / DN_BM, NE);
    down_kernel<<<gd, 256>>>();

    int n4 = T_TOK * (H / 4);
    combine_kernel<<<(n4 + 255) / 256, 256>>>(x, out);
}

// round 15
// speedup vs baseline: 2.0904x; 1.0800x over previous
#include <cuda_runtime.h>
#include <cuda_fp16.h>
#include <math.h>
#include <stdint.h>

#define T_TOK 4096
#define H     2048
#define IDIM  1024
#define NE    8
#define NTOT  12
#define CAP   4096
#define SCALE 1.5f

// ---------------- scratch (static device globals; no runtime allocation) ----------------
__device__ int   g_cnt[NE];
__device__ int   g_tok[NE * CAP];
__device__ float g_wt [NE * CAP];
__device__ int   g_dst[NE * CAP];
__device__ float g_zw [T_TOK];
__device__ int   g_mask[T_TOK];
__device__ __half g_hx [(size_t)T_TOK * H];           // fp16 hidden states
__device__ __half g_hgw[(size_t)NE * IDIM * H];       // fp16 gate weights
__device__ __half g_huw[(size_t)NE * IDIM * H];       // fp16 up weights
__device__ __half g_hdw[(size_t)NE * H * IDIM];       // fp16 down weights
__device__ __half g_act[(size_t)NE * CAP * IDIM];     // fp16 expert-grouped activations
__device__ float g_pair[(size_t)T_TOK * 2 * H];       // per (token,k) down output (fp32)

// ---------------- helpers ----------------
__device__ __forceinline__ void cp_async16(void* smem, const void* gmem) {
    uint32_t s = (uint32_t)__cvta_generic_to_shared(smem);
    asm volatile("cp.async.cg.shared.global [%0], [%1], 16;" :: "r"(s), "l"(gmem));
}
#define CP_COMMIT() asm volatile("cp.async.commit_group;")
#define CP_WAIT0()  asm volatile("cp.async.wait_group 0;")

__device__ __forceinline__ uint32_t smem_u32(const void* p) {
    return (uint32_t)__cvta_generic_to_shared(p);
}

__device__ __forceinline__ uint32_t pack2(float a, float b) {
    __half2 h = __floats2half2_rn(a, b);
    return *reinterpret_cast<uint32_t*>(&h);
}

#define LDSM_X4(r0, r1, r2, r3, addr) \
    asm volatile("ldmatrix.sync.aligned.m8n8.x4.shared.b16 {%0,%1,%2,%3}, [%4];" \
                 : "=r"(r0), "=r"(r1), "=r"(r2), "=r"(r3) : "r"(addr))

__device__ __forceinline__ void mma_f16(float c[4],
                                        uint32_t a0, uint32_t a1, uint32_t a2, uint32_t a3,
                                        uint32_t b0, uint32_t b1) {
    asm volatile(
        "mma.sync.aligned.m16n8k16.row.col.f32.f16.f16.f32 "
        "{%0,%1,%2,%3}, {%4,%5,%6,%7}, {%8,%9}, {%0,%1,%2,%3};\n"
        : "+f"(c[0]), "+f"(c[1]), "+f"(c[2]), "+f"(c[3])
        : "r"(a0), "r"(a1), "r"(a2), "r"(a3), "r"(b0), "r"(b1));
}

// ---------------- fp32 -> fp16 conversion (16B granules) ----------------
__global__ void cvt_kernel(const float* __restrict__ src, __half* __restrict__ dst, int n8) {
    int i = blockIdx.x * blockDim.x + threadIdx.x;   // one per 8 elements
    if (i >= n8) return;
    const float4* s4 = (const float4*)src + (size_t)i * 2;
    float4 a = s4[0], b = s4[1];
    uint4 o;
    o.x = pack2(a.x, a.y); o.y = pack2(a.z, a.w);
    o.z = pack2(b.x, b.y); o.w = pack2(b.z, b.w);
    ((uint4*)dst)[i] = o;
}

// ---------------- router: one warp per token (fp32 — exact expert selection) ----------------
__global__ void router_kernel(const float* __restrict__ x,
                              const float* __restrict__ cw,
                              const float* __restrict__ bias) {
    int warp = threadIdx.x >> 5;
    int lane = threadIdx.x & 31;
    int t = blockIdx.x * 4 + warp;
    if (t >= T_TOK) return;
    const float* xr = x + (size_t)t * H;

    float acc[NTOT];
#pragma unroll
    for (int e = 0; e < NTOT; e++) acc[e] = 0.f;
    for (int h = lane; h < H; h += 32) {
        float xv = xr[h];
#pragma unroll
        for (int e = 0; e < NTOT; e++) acc[e] += xv * __ldg(&cw[e * H + h]);
    }
#pragma unroll
    for (int e = 0; e < NTOT; e++) {
#pragma unroll
        for (int off = 16; off; off >>= 1)
            acc[e] += __shfl_xor_sync(0xffffffffu, acc[e], off);
    }
    if (lane == 0) {
        float m = acc[0];
#pragma unroll
        for (int e = 1; e < NTOT; e++) m = fmaxf(m, acc[e]);
        float p[NTOT];
        float s = 0.f;
#pragma unroll
        for (int e = 0; e < NTOT; e++) { p[e] = expf(acc[e] - m); s += p[e]; }
        float inv = 1.f / s;
        float biased[NTOT];
#pragma unroll
        for (int e = 0; e < NTOT; e++) { p[e] *= inv; biased[e] = p[e] + bias[e]; }

        // top-2 of biased scores (lowest index wins ties, matching jax.lax.top_k)
        int i0 = 0;
#pragma unroll
        for (int e = 1; e < NTOT; e++) if (biased[e] > biased[i0]) i0 = e;
        int i1 = (i0 == 0) ? 1 : 0;
#pragma unroll
        for (int e = 0; e < NTOT; e++)
            if (e != i0 && biased[e] > biased[i1]) i1 = e;

        int sel[2] = { i0, i1 };
        float zw = 0.f;
        int mask = 0;
#pragma unroll
        for (int k = 0; k < 2; k++) {
            int e = sel[k];
            float w = p[e] * SCALE;       // weight uses UNBIASED prob
            if (e < NE) {
                int slot = atomicAdd(&g_cnt[e], 1);
                g_tok[e * CAP + slot] = t;
                g_wt [e * CAP + slot] = w;
                g_dst[e * CAP + slot] = t * 2 + k;
                mask |= (1 << k);
            } else {
                zw += w;
            }
        }
        g_zw[t]  = zw;
        g_mask[t] = mask;
    }
}

// ---------------- gateup fp16 GEMM (ldmatrix + m16n8k16), BK=64, fused SiLU ----------------
// Block tile: 128 slots x 64 inter. 8 warps (4x2). Warp 32x32 both mats.
#define GU_BM 128
#define GU_BN 64
#define GU_BK 64
#define GU_IT (H / GU_BK)     // 32
#define SMSH 72               // smem row stride (halves): 144B -> conflict-free ldmatrix
#define GU_A_HALF (GU_BM * SMSH)
#define GU_B_HALF (GU_BN * SMSH)
#define GU_STAGE_HALF (GU_A_HALF + 2 * GU_B_HALF)
#define GU_SMEM_BYTES (2 * GU_STAGE_HALF * 2 + GU_BM * 4)

__global__ __launch_bounds__(256, 2) void gateup_kernel() {
    int e = blockIdx.z;
    int cnt = g_cnt[e];
    int t0 = blockIdx.y * GU_BM;
    if (t0 >= cnt) return;
    int i0 = blockIdx.x * GU_BN;

    extern __shared__ __half dsm[];
    __half* SA[2] = { dsm,                          dsm + GU_STAGE_HALF };
    __half* SG[2] = { dsm + GU_A_HALF,              dsm + GU_STAGE_HALF + GU_A_HALF };
    __half* SU[2] = { dsm + GU_A_HALF + GU_B_HALF,  dsm + GU_STAGE_HALF + GU_A_HALF + GU_B_HALF };
    int* toks = (int*)(dsm + 2 * GU_STAGE_HALF);

    int tid  = threadIdx.x;
    int lane = tid & 31;
    int warp = tid >> 5;
    int wm = warp >> 1;       // 0..3 (m 32 rows each)
    int wn = warp & 1;        // 0..1 (n 32 cols each)

    if (tid < GU_BM) {
        int s = t0 + tid;
        toks[tid] = g_tok[e * CAP + ((s < cnt) ? s : 0)];
    }
    __syncthreads();

    const __half* gw_e = g_hgw + (size_t)e * IDIM * H + (size_t)i0 * H;
    const __half* uw_e = g_huw + (size_t)e * IDIM * H + (size_t)i0 * H;

    // fragment base addresses and offsets
    uint32_t saB[2] = { smem_u32(SA[0]), smem_u32(SA[1]) };
    uint32_t sgB[2] = { smem_u32(SG[0]), smem_u32(SG[1]) };
    uint32_t suB[2] = { smem_u32(SU[0]), smem_u32(SU[1]) };
    uint32_t offA[2], offB[2];
#pragma unroll
    for (int mi = 0; mi < 2; mi++)
        offA[mi] = ((wm * 32 + mi * 16 + (lane & 15)) * SMSH + (lane >> 4) * 8) * 2;
#pragma unroll
    for (int nt = 0; nt < 2; nt++)
        offB[nt] = ((wn * 32 + nt * 16 + (lane & 7) + ((lane >> 4) << 3)) * SMSH
                    + ((lane >> 3) & 1) * 8) * 2;

    float cg[2][4][4] = {};
    float cu[2][4][4] = {};

    // fill: 64 halves per row = 8 chunks of 8; A: 1024 chunks (4/thr), G/U: 512 (2/thr)
    auto fill = [&](int st, int k0) {
#pragma unroll
        for (int c = 0; c < 4; c++) {
            int id = c * 256 + tid;
            int r = id >> 3, j = (id & 7) * 8;
            cp_async16(&SA[st][r * SMSH + j], g_hx + (size_t)toks[r] * H + k0 + j);
        }
#pragma unroll
        for (int c = 0; c < 2; c++) {
            int id = c * 256 + tid;
            int r = id >> 3, j = (id & 7) * 8;
            cp_async16(&SG[st][r * SMSH + j], gw_e + (size_t)r * H + k0 + j);
            cp_async16(&SU[st][r * SMSH + j], uw_e + (size_t)r * H + k0 + j);
        }
    };

    fill(0, 0); CP_COMMIT();

    for (int k = 0; k < GU_IT; k++) {
        CP_WAIT0();
        __syncthreads();

        int kn = k + 1;
        if (kn < GU_IT) fill(kn & 1, kn * GU_BK);
        CP_COMMIT();

        int st = k & 1;
#pragma unroll
        for (int ks = 0; ks < GU_BK / 16; ks++) {
            uint32_t a[2][4];
#pragma unroll
            for (int mi = 0; mi < 2; mi++)
                LDSM_X4(a[mi][0], a[mi][1], a[mi][2], a[mi][3], saB[st] + offA[mi] + ks * 32);
#pragma unroll
            for (int nt = 0; nt < 2; nt++) {
                uint32_t bg[4], bu[4];
                LDSM_X4(bg[0], bg[1], bg[2], bg[3], sgB[st] + offB[nt] + ks * 32);
                LDSM_X4(bu[0], bu[1], bu[2], bu[3], suB[st] + offB[nt] + ks * 32);
#pragma unroll
                for (int h = 0; h < 2; h++) {
                    int ni = nt * 2 + h;
#pragma unroll
                    for (int mi = 0; mi < 2; mi++) {
                        mma_f16(cg[mi][ni], a[mi][0], a[mi][1], a[mi][2], a[mi][3], bg[2 * h], bg[2 * h + 1]);
                        mma_f16(cu[mi][ni], a[mi][0], a[mi][1], a[mi][2], a[mi][3], bu[2 * h], bu[2 * h + 1]);
                    }
                }
            }
        }
    }

    // epilogue: act = silu(gate) * up -> fp16
#pragma unroll
    for (int mi = 0; mi < 2; mi++) {
        int r0 = wm * 32 + mi * 16 + (lane >> 2);
        int srow0 = t0 + r0;
        int srow1 = srow0 + 8;
        __half* row0 = g_act + ((size_t)e * CAP + srow0) * IDIM + i0;
        __half* row1 = g_act + ((size_t)e * CAP + srow1) * IDIM + i0;
#pragma unroll
        for (int ni = 0; ni < 4; ni++) {
            int col = wn * 32 + ni * 8 + (lane & 3) * 2;
            if (srow0 < cnt) {
                float g0 = cg[mi][ni][0], g1 = cg[mi][ni][1];
                float v0 = (g0 / (1.f + expf(-g0))) * cu[mi][ni][0];
                float v1 = (g1 / (1.f + expf(-g1))) * cu[mi][ni][1];
                *(uint32_t*)(row0 + col) = pack2(v0, v1);
            }
            if (srow1 < cnt) {
                float g2 = cg[mi][ni][2], g3 = cg[mi][ni][3];
                float v2 = (g2 / (1.f + expf(-g2))) * cu[mi][ni][2];
                float v3 = (g3 / (1.f + expf(-g3))) * cu[mi][ni][3];
                *(uint32_t*)(row1 + col) = pack2(v2, v3);
            }
        }
    }
}

// ---------------- down fp16 GEMM (ldmatrix + m16n8k16), BK=64, weight-scaled scatter ----------------
// Block tile: 128 slots x 128 H. 8 warps (4x2). Warp 32x64.
#define DN_BM 128
#define DN_BN 128
#define DN_BK 64
#define DN_IT (IDIM / DN_BK)   // 16
#define DN_T_HALF (DN_BM * SMSH)
#define DN_STAGE_HALF (2 * DN_T_HALF)
#define DN_SMEM_BYTES (2 * DN_STAGE_HALF * 2 + DN_BM * 8)

__global__ __launch_bounds__(256, 2) void down_kernel() {
    int e = blockIdx.z;
    int cnt = g_cnt[e];
    int s0 = blockIdx.y * DN_BM;
    if (s0 >= cnt) return;
    int h0 = blockIdx.x * DN_BN;

    extern __shared__ __half dsm[];
    __half* SA[2] = { dsm,              dsm + DN_STAGE_HALF };
    __half* SB[2] = { dsm + DN_T_HALF,  dsm + DN_STAGE_HALF + DN_T_HALF };
    float* wts = (float*)(dsm + 2 * DN_STAGE_HALF);
    int* dsts = (int*)(wts + DN_BM);

    int tid  = threadIdx.x;
    int lane = tid & 31;
    int warp = tid >> 5;
    int wm = warp >> 1;      // 0..3
    int wn = warp & 1;       // 0..1 (n 64 each)

    if (tid < DN_BM) {
        int s = s0 + tid;
        int cs = (s < cnt) ? s : 0;
        wts[tid]  = g_wt [e * CAP + cs];
        dsts[tid] = g_dst[e * CAP + cs];
    }
    __syncthreads();

    const __half* aBase = g_act + ((size_t)e * CAP + s0) * IDIM;
    const __half* bBase = g_hdw + (size_t)e * H * IDIM + (size_t)h0 * IDIM;

    uint32_t saB[2] = { smem_u32(SA[0]), smem_u32(SA[1]) };
    uint32_t sbB[2] = { smem_u32(SB[0]), smem_u32(SB[1]) };
    uint32_t offA[2], offB[4];
#pragma unroll
    for (int mi = 0; mi < 2; mi++)
        offA[mi] = ((wm * 32 + mi * 16 + (lane & 15)) * SMSH + (lane >> 4) * 8) * 2;
#pragma unroll
    for (int nt = 0; nt < 4; nt++)
        offB[nt] = ((wn * 64 + nt * 16 + (lane & 7) + ((lane >> 4) << 3)) * SMSH
                    + ((lane >> 3) & 1) * 8) * 2;

    float acc[2][8][4] = {};

    auto fill = [&](int st, int k0) {
#pragma unroll
        for (int c = 0; c < 4; c++) {
            int id = c * 256 + tid;
            int r = id >> 3, j = (id & 7) * 8;
            cp_async16(&SA[st][r * SMSH + j], aBase + (size_t)r * IDIM + k0 + j);
            cp_async16(&SB[st][r * SMSH + j], bBase + (size_t)r * IDIM + k0 + j);
        }
    };

    fill(0, 0); CP_COMMIT();

    for (int k = 0; k < DN_IT; k++) {
        CP_WAIT0();
        __syncthreads();

        int kn = k + 1;
        if (kn < DN_IT) fill(kn & 1, kn * DN_BK);
        CP_COMMIT();

        int st = k & 1;
#pragma unroll
        for (int ks = 0; ks < DN_BK / 16; ks++) {
            uint32_t a[2][4];
#pragma unroll
            for (int mi = 0; mi < 2; mi++)
                LDSM_X4(a[mi][0], a[mi][1], a[mi][2], a[mi][3], saB[st] + offA[mi] + ks * 32);
#pragma unroll
            for (int nt = 0; nt < 4; nt++) {
                uint32_t b[4];
                LDSM_X4(b[0], b[1], b[2], b[3], sbB[st] + offB[nt] + ks * 32);
#pragma unroll
                for (int h = 0; h < 2; h++) {
                    int ni = nt * 2 + h;
#pragma unroll
                    for (int mi = 0; mi < 2; mi++)
                        mma_f16(acc[mi][ni], a[mi][0], a[mi][1], a[mi][2], a[mi][3], b[2 * h], b[2 * h + 1]);
                }
            }
        }
    }

#pragma unroll
    for (int mi = 0; mi < 2; mi++) {
        int r0 = wm * 32 + mi * 16 + (lane >> 2);
        int r1 = r0 + 8;
        int srow0 = s0 + r0;
        int srow1 = s0 + r1;
        float w0 = wts[r0], w1 = wts[r1];
        float* o0 = g_pair + (size_t)dsts[r0] * H + h0;
        float* o1 = g_pair + (size_t)dsts[r1] * H + h0;
#pragma unroll
        for (int ni = 0; ni < 8; ni++) {
            int col = wn * 64 + ni * 8 + (lane & 3) * 2;
            if (srow0 < cnt) {
                float2 v = { acc[mi][ni][0] * w0, acc[mi][ni][1] * w0 };
                *(float2*)(o0 + col) = v;
            }
            if (srow1 < cnt) {
                float2 v = { acc[mi][ni][2] * w1, acc[mi][ni][3] * w1 };
                *(float2*)(o1 + col) = v;
            }
        }
    }
}

// ---------------- combine: out = x*zero_w + valid pair contributions ----------------
__global__ void combine_kernel(const float* __restrict__ x, float* __restrict__ out) {
    int idx = blockIdx.x * blockDim.x + threadIdx.x;
    if (idx >= T_TOK * (H / 4)) return;
    int t  = idx / (H / 4);
    int h4 = idx % (H / 4);
    float4 xv = ((const float4*)x)[idx];
    float zw = g_zw[t];
    int mask = g_mask[t];
    float4 r;
    r.x = xv.x * zw; r.y = xv.y * zw; r.z = xv.z * zw; r.w = xv.w * zw;
    if (mask & 1) {
        float4 p = ((const float4*)(g_pair + (size_t)(t * 2) * H))[h4];
        r.x += p.x; r.y += p.y; r.z += p.z; r.w += p.w;
    }
    if (mask & 2) {
        float4 p = ((const float4*)(g_pair + (size_t)(t * 2 + 1) * H))[h4];
        r.x += p.x; r.y += p.y; r.z += p.z; r.w += p.w;
    }
    ((float4*)out)[idx] = r;
}

// ---------------- launch ----------------
extern "C" void kernel_launch(void* const* d_in, const int* in_sizes, int n_in,
                              void* d_out, int out_size) {
    const float* x    = (const float*)d_in[0];
    const float* cw   = (const float*)d_in[1];
    const float* bias = (const float*)d_in[2];
    const float* gw   = (const float*)d_in[3];
    const float* uw   = (const float*)d_in[4];
    const float* dw   = (const float*)d_in[5];
    float* out = (float*)d_out;

    cudaFuncSetAttribute(gateup_kernel, cudaFuncAttributeMaxDynamicSharedMemorySize, GU_SMEM_BYTES);
    cudaFuncSetAttribute(down_kernel,   cudaFuncAttributeMaxDynamicSharedMemorySize, DN_SMEM_BYTES);

    void* cntAddr = nullptr;
    cudaGetSymbolAddress(&cntAddr, g_cnt);
    cudaMemsetAsync(cntAddr, 0, NE * sizeof(int));

    // fp32 -> fp16 conversions
    void* p;
    cudaGetSymbolAddress(&p, g_hx);
    { int n8 = T_TOK * H / 8;        cvt_kernel<<<(n8 + 255) / 256, 256>>>(x,  (__half*)p, n8); }
    cudaGetSymbolAddress(&p, g_hgw);
    { int n8 = NE * IDIM * H / 8;    cvt_kernel<<<(n8 + 255) / 256, 256>>>(gw, (__half*)p, n8); }
    cudaGetSymbolAddress(&p, g_huw);
    { int n8 = NE * IDIM * H / 8;    cvt_kernel<<<(n8 + 255) / 256, 256>>>(uw, (__half*)p, n8); }
    cudaGetSymbolAddress(&p, g_hdw);
    { int n8 = NE * H * IDIM / 8;    cvt_kernel<<<(n8 + 255) / 256, 256>>>(dw, (__half*)p, n8); }

    router_kernel<<<T_TOK / 4, 128>>>(x, cw, bias);

    dim3 gb(IDIM / GU_BN, T_TOK / GU_BM, NE);
    gateup_kernel<<<gb, 256, GU_SMEM_BYTES>>>();

    dim3 gd(H / DN_BN, T_TOK / DN_BM, NE);
    down_kernel<<<gd, 256, DN_SMEM_BYTES>>>();

    int n4 = T_TOK * (H / 4);
    combine_kernel<<<(n4 + 255) / 256, 256>>>(x, out);
}